// round 7
// baseline (speedup 1.0000x reference)
#include <cuda_runtime.h>
#include <cstdint>

#define Bc 2
#define Tc 2048
#define Cc 1024
#define Hc 16
#define Dc 64

__device__ float g_q[Bc * Hc * Tc * Dc];
__device__ float g_k[Bc * Hc * Tc * Dc];
__device__ float g_v[Bc * Hc * Tc * Dc];
__device__ float g_y[Bc * Tc * Cc];

// ---------------- packed f32x2 helpers ----------------
typedef unsigned long long u64t;
__device__ __forceinline__ u64t ffma2(u64t a, u64t b, u64t c) {
    u64t d; asm("fma.rn.f32x2 %0, %1, %2, %3;" : "=l"(d) : "l"(a), "l"(b), "l"(c)); return d;
}
__device__ __forceinline__ u64t fmul2(u64t a, u64t b) {
    u64t d; asm("mul.rn.f32x2 %0, %1, %2;" : "=l"(d) : "l"(a), "l"(b)); return d;
}
__device__ __forceinline__ u64t pk2(float x, float y) {
    u64t r; asm("mov.b64 %0, {%1, %2};" : "=l"(r) : "f"(x), "f"(y)); return r;
}
__device__ __forceinline__ void up2(u64t v, float& x, float& y) {
    asm("mov.b64 {%0, %1}, %2;" : "=f"(x), "=f"(y) : "l"(v));
}

// ============================================================================
// NT GEMM: C[m,n] = sum_k A[m,k]*B[n,k] + bias[n]. fp32, f32x2-packed FMA.
// CTA 128x128, K chunk 16, register prefetch, 8x8 per-thread tile
// (acc packed as 8x4 u64 pairs over n). MODE 0: scatter [B,H,T,D]; 1: [M,N].
// ============================================================================
#define GBM 128
#define GBN 128
#define GBK 16

template <int MODE>
__global__ void __launch_bounds__(256)
gemm_nt(const float* __restrict__ A, const float* __restrict__ B,
        const float* __restrict__ bias, float* __restrict__ C,
        int M, int N, int K)
{
    __shared__ __align__(16) float As[GBK][GBM];
    __shared__ __align__(16) float Bs[GBK][GBN];

    const int tid = threadIdx.x;
    const int m0 = blockIdx.y * GBM;
    const int n0 = blockIdx.x * GBN;
    const int row = (tid >> 4) << 3;
    const int col = (tid & 15) << 3;

    u64t acc2[8][4];
#pragma unroll
    for (int i = 0; i < 8; i++)
#pragma unroll
        for (int j = 0; j < 4; j++) acc2[i][j] = 0ull;

    float4 ra[2], rb[2];
#pragma unroll
    for (int it = 0; it < 2; it++) {
        int e = tid + it * 256;
        int r = e >> 2, c4 = (e & 3) << 2;
        ra[it] = *reinterpret_cast<const float4*>(&A[(size_t)(m0 + r) * K + c4]);
        rb[it] = *reinterpret_cast<const float4*>(&B[(size_t)(n0 + r) * K + c4]);
    }

    for (int k0 = 0; k0 < K; k0 += GBK) {
#pragma unroll
        for (int it = 0; it < 2; it++) {
            int e = tid + it * 256;
            int r = e >> 2, c4 = (e & 3) << 2;
            As[c4 + 0][r] = ra[it].x; As[c4 + 1][r] = ra[it].y;
            As[c4 + 2][r] = ra[it].z; As[c4 + 3][r] = ra[it].w;
            Bs[c4 + 0][r] = rb[it].x; Bs[c4 + 1][r] = rb[it].y;
            Bs[c4 + 2][r] = rb[it].z; Bs[c4 + 3][r] = rb[it].w;
        }
        __syncthreads();

        if (k0 + GBK < K) {
#pragma unroll
            for (int it = 0; it < 2; it++) {
                int e = tid + it * 256;
                int r = e >> 2, c4 = (e & 3) << 2;
                ra[it] = *reinterpret_cast<const float4*>(&A[(size_t)(m0 + r) * K + k0 + GBK + c4]);
                rb[it] = *reinterpret_cast<const float4*>(&B[(size_t)(n0 + r) * K + k0 + GBK + c4]);
            }
        }

#pragma unroll
        for (int k = 0; k < GBK; k++) {
            float a[8];
            *reinterpret_cast<float4*>(&a[0]) = *reinterpret_cast<const float4*>(&As[k][row]);
            *reinterpret_cast<float4*>(&a[4]) = *reinterpret_cast<const float4*>(&As[k][row + 4]);
            ulonglong2 b01 = *reinterpret_cast<const ulonglong2*>(&Bs[k][col]);
            ulonglong2 b23 = *reinterpret_cast<const ulonglong2*>(&Bs[k][col + 4]);
            u64t bb[4] = {b01.x, b01.y, b23.x, b23.y};
#pragma unroll
            for (int i = 0; i < 8; i++) {
                u64t ad = pk2(a[i], a[i]);
#pragma unroll
                for (int j = 0; j < 4; j++) acc2[i][j] = ffma2(ad, bb[j], acc2[i][j]);
            }
        }
        __syncthreads();
    }

#pragma unroll
    for (int i = 0; i < 8; i++) {
        int m = m0 + row + i;
        float v[8];
#pragma unroll
        for (int j = 0; j < 4; j++) up2(acc2[i][j], v[2 * j], v[2 * j + 1]);
#pragma unroll
        for (int j = 0; j < 8; j++) {
            int n = n0 + col + j;
            float val = v[j] + bias[n];
            if (MODE == 0) {
                int bb = m >> 11, tt = m & 2047, hh = n >> 6, dd = n & 63;
                C[((size_t)((bb * Hc + hh) * Tc + tt) << 6) + dd] = val;
            } else {
                C[(size_t)m * N + n] = val;
            }
        }
    }
}

// ============================================================================
// Flash attention fp32, causal, 64q x 64kv tiles, 256 threads.
// Thread (qg=tid>>4, kg=tid&15): scores 4q x 4k block (rows 4qg.., cols 4kg..),
// output 4q x 4d block (dims 4kg..). Scores exchanged via transposed smem P.
// Swizzle: float4 col' = c4 ^ ((row + row>>4) & 15)  -> conflict-free for all
// row-strided access patterns used here.
// ============================================================================
__device__ __forceinline__ int swf(int row, int c4) {
    return (row << 4) + (c4 ^ ((row + (row >> 4)) & 15));
}

#define FSMEM_BYTES (4 * 64 * 64 * 4)   // Qs,Ks,Vs,Ps = 64KB

__global__ void __launch_bounds__(256)
flash_attn(const float* __restrict__ Q, const float* __restrict__ K,
           const float* __restrict__ V, float* __restrict__ Y)
{
    extern __shared__ __align__(16) float fs[];
    float* Qs = fs;
    float* Ks = fs + 4096;
    float* Vs = fs + 8192;
    float* Ps = fs + 12288;

    const int bh  = blockIdx.y;
    const int b   = bh >> 4;
    const int h   = bh & 15;
    const int qtile = gridDim.x - 1 - blockIdx.x;   // longest blocks first
    const int m0  = qtile << 6;
    const int tid = threadIdx.x;
    const int qg  = tid >> 4;      // 0..15
    const int kg  = tid & 15;      // 0..15
    const int q0  = qg << 2;
    const size_t base = (size_t)bh * Tc * Dc;

    // load Q tile (pre-scaled by 1/sqrt(D))
#pragma unroll
    for (int it = 0; it < 4; it++) {
        int e = tid + (it << 8);
        int rr = e >> 4, c4 = e & 15;
        float4 v = *(const float4*)&Q[base + (size_t)(m0 + rr) * Dc + (c4 << 2)];
        v.x *= 0.125f; v.y *= 0.125f; v.z *= 0.125f; v.w *= 0.125f;
        ((float4*)Qs)[swf(rr, c4)] = v;
    }

    u64t acc2[4][2];
#pragma unroll
    for (int i = 0; i < 4; i++) { acc2[i][0] = 0ull; acc2[i][1] = 0ull; }
    float m[4], l[4];
#pragma unroll
    for (int i = 0; i < 4; i++) { m[i] = -1e30f; l[i] = 0.f; }

    const int nkv = qtile + 1;
    for (int j = 0; j < nkv; j++) {
        const int n0 = j << 6;
        __syncthreads();   // protect Ks/Vs/Ps from previous iter readers
#pragma unroll
        for (int it = 0; it < 4; it++) {
            int e = tid + (it << 8);
            int rr = e >> 4, c4 = e & 15;
            ((float4*)Ks)[swf(rr, c4)] =
                *(const float4*)&K[base + (size_t)(n0 + rr) * Dc + (c4 << 2)];
            ((float4*)Vs)[swf(rr, c4)] =
                *(const float4*)&V[base + (size_t)(n0 + rr) * Dc + (c4 << 2)];
        }
        __syncthreads();

        // ---- QK: s[qi][kj] = Q[q0+qi,:] . K[4kg+kj,:] (packed over d) ----
        u64t s2[4][4];
#pragma unroll
        for (int qi = 0; qi < 4; qi++)
#pragma unroll
            for (int kj = 0; kj < 4; kj++) s2[qi][kj] = 0ull;
#pragma unroll
        for (int c4 = 0; c4 < 16; c4++) {
            ulonglong2 q2[4], k2[4];
#pragma unroll
            for (int qi = 0; qi < 4; qi++)
                q2[qi] = ((const ulonglong2*)Qs)[swf(q0 + qi, c4)];
#pragma unroll
            for (int kj = 0; kj < 4; kj++)
                k2[kj] = ((const ulonglong2*)Ks)[swf((kg << 2) + kj, c4)];
#pragma unroll
            for (int qi = 0; qi < 4; qi++)
#pragma unroll
                for (int kj = 0; kj < 4; kj++) {
                    s2[qi][kj] = ffma2(q2[qi].x, k2[kj].x, s2[qi][kj]);
                    s2[qi][kj] = ffma2(q2[qi].y, k2[kj].y, s2[qi][kj]);
                }
        }
        float s[4][4];
#pragma unroll
        for (int qi = 0; qi < 4; qi++)
#pragma unroll
            for (int kj = 0; kj < 4; kj++) {
                float a, bb; up2(s2[qi][kj], a, bb);
                s[qi][kj] = a + bb;
            }

        // causal mask (diagonal tile only)
        if (j == nkv - 1) {
#pragma unroll
            for (int qi = 0; qi < 4; qi++)
#pragma unroll
                for (int kj = 0; kj < 4; kj++)
                    if (((kg << 2) + kj) > (q0 + qi)) s[qi][kj] = -1e30f;
        }

        // ---- online softmax (reduce across the 16 kg lanes) ----
        float mx[4];
#pragma unroll
        for (int qi = 0; qi < 4; qi++)
            mx[qi] = fmaxf(fmaxf(s[qi][0], s[qi][1]), fmaxf(s[qi][2], s[qi][3]));
#pragma unroll
        for (int off = 1; off < 16; off <<= 1)
#pragma unroll
            for (int qi = 0; qi < 4; qi++)
                mx[qi] = fmaxf(mx[qi], __shfl_xor_sync(0xffffffffu, mx[qi], off));

        float alpha[4], sum[4];
#pragma unroll
        for (int qi = 0; qi < 4; qi++) {
            float mn = fmaxf(m[qi], mx[qi]);
            alpha[qi] = __expf(m[qi] - mn);
            m[qi] = mn;
            float t0 = __expf(s[qi][0] - mn);
            float t1 = __expf(s[qi][1] - mn);
            float t2 = __expf(s[qi][2] - mn);
            float t3 = __expf(s[qi][3] - mn);
            s[qi][0] = t0; s[qi][1] = t1; s[qi][2] = t2; s[qi][3] = t3;
            sum[qi] = (t0 + t1) + (t2 + t3);
        }
#pragma unroll
        for (int off = 1; off < 16; off <<= 1)
#pragma unroll
            for (int qi = 0; qi < 4; qi++)
                sum[qi] += __shfl_xor_sync(0xffffffffu, sum[qi], off);
#pragma unroll
        for (int qi = 0; qi < 4; qi++) {
            l[qi] = l[qi] * alpha[qi] + sum[qi];
            u64t a2 = pk2(alpha[qi], alpha[qi]);
            acc2[qi][0] = fmul2(acc2[qi][0], a2);
            acc2[qi][1] = fmul2(acc2[qi][1], a2);
        }

        // ---- store P transposed: Ps[c][q] ----
#pragma unroll
        for (int kj = 0; kj < 4; kj++) {
            float4 pv = make_float4(s[0][kj], s[1][kj], s[2][kj], s[3][kj]);
            ((float4*)Ps)[swf((kg << 2) + kj, qg)] = pv;
        }
        __syncthreads();

        // ---- PV: acc[qi][d] += P[q0+qi][c] * V[c][4kg+d] ----
#pragma unroll 8
        for (int c = 0; c < 64; c++) {
            float4 p4 = ((const float4*)Ps)[swf(c, qg)];
            ulonglong2 v2 = ((const ulonglong2*)Vs)[swf(c, kg)];
            u64t pd;
            pd = pk2(p4.x, p4.x);
            acc2[0][0] = ffma2(pd, v2.x, acc2[0][0]);
            acc2[0][1] = ffma2(pd, v2.y, acc2[0][1]);
            pd = pk2(p4.y, p4.y);
            acc2[1][0] = ffma2(pd, v2.x, acc2[1][0]);
            acc2[1][1] = ffma2(pd, v2.y, acc2[1][1]);
            pd = pk2(p4.z, p4.z);
            acc2[2][0] = ffma2(pd, v2.x, acc2[2][0]);
            acc2[2][1] = ffma2(pd, v2.y, acc2[2][1]);
            pd = pk2(p4.w, p4.w);
            acc2[3][0] = ffma2(pd, v2.x, acc2[3][0]);
            acc2[3][1] = ffma2(pd, v2.y, acc2[3][1]);
        }
    }

    // ---- output ----
#pragma unroll
    for (int qi = 0; qi < 4; qi++) {
        float inv = 1.0f / l[qi];
        float x0, x1, x2, x3;
        up2(acc2[qi][0], x0, x1);
        up2(acc2[qi][1], x2, x3);
        const size_t orow = (size_t)(b * Tc + m0 + q0 + qi) * Cc + (h << 6) + (kg << 2);
        *(float4*)&Y[orow] = make_float4(x0 * inv, x1 * inv, x2 * inv, x3 * inv);
    }
}

// ============================================================================
extern "C" void kernel_launch(void* const* d_in, const int* in_sizes, int n_in,
                              void* d_out, int out_size)
{
    const float* x  = (const float*)d_in[0];
    const float* Wk = (const float*)d_in[1];
    const float* bk = (const float*)d_in[2];
    const float* Wq = (const float*)d_in[3];
    const float* bq = (const float*)d_in[4];
    const float* Wv = (const float*)d_in[5];
    const float* bv = (const float*)d_in[6];
    const float* Wp = (const float*)d_in[7];
    const float* bp = (const float*)d_in[8];
    float* out = (float*)d_out;

    float *pq, *pk, *pv, *py;
    cudaGetSymbolAddress((void**)&pq, g_q);
    cudaGetSymbolAddress((void**)&pk, g_k);
    cudaGetSymbolAddress((void**)&pv, g_v);
    cudaGetSymbolAddress((void**)&py, g_y);

    cudaFuncSetAttribute(flash_attn, cudaFuncAttributeMaxDynamicSharedMemorySize, FSMEM_BYTES);

    const int M = Bc * Tc, N = Cc, K = Cc;

    dim3 gg(N / GBN, M / GBM);   // (8, 32)
    gemm_nt<0><<<gg, 256>>>(x, Wq, bq, pq, M, N, K);
    gemm_nt<0><<<gg, 256>>>(x, Wk, bk, pk, M, N, K);
    gemm_nt<0><<<gg, 256>>>(x, Wv, bv, pv, M, N, K);

    dim3 fg(Tc / 64, Bc * Hc);   // (32, 32)
    flash_attn<<<fg, 256, FSMEM_BYTES>>>(pq, pk, pv, py);

    gemm_nt<1><<<gg, 256>>>(py, Wp, bp, out, M, N, K);
}